// round 6
// baseline (speedup 1.0000x reference)
#include <cuda_runtime.h>
#include <cstdint>

// Neighborlist brute N^2, upper-triangular pairs, PBC minimum image.
// N=6000 -> P = 17,997,000 pairs.
// Output buffer: float32, concatenation of the reference tuple:
//   [0,    P)   : masked i indices (-1 if out of cutoff)
//   [P,   2P)   : masked j indices
//   [2P,  3P)   : d_ij (0 if out of cutoff)
//   [3P,  6P)   : r_ij row-major [P,3] (0 if out of cutoff)

#define N_PART   6000
#define P_TOTAL  17997000LL   // N*(N-1)/2
#define CUTOFF_F 0.5f

__device__ __forceinline__ long long row_off(int i) {
    // offset of first pair of row i in triu(k=1) ordering
    return (long long)i * (2 * N_PART - i - 1) / 2;
}

// Matches jnp.remainder(x, L) for L > 0 (floor-mod):
//   m = fmod(x, L); if (m != 0 && m < 0) m += L;   (fmod is exact)
__device__ __forceinline__ float floormod_wrap(float r, float L, float halfL) {
    float t = __fadd_rn(r, halfL);         // (r + half), round-to-nearest, no fusion
    float m = fmodf(t, L);
    if (m != 0.0f && m < 0.0f) m = __fadd_rn(m, L);
    return __fadd_rn(m, -halfL);           // m - half
}

__global__ __launch_bounds__(256)
void neighborlist_kernel(const float* __restrict__ pos,
                         const float* __restrict__ box,
                         const int* __restrict__ is_periodic,
                         float* __restrict__ out)
{
    long long p = (long long)blockIdx.x * blockDim.x + threadIdx.x;
    if (p >= P_TOTAL) return;

    // ---- invert linear pair index p -> (i, j), i < j ----
    // off(i) = i*(2N-1-i)/2 <= p  =>  i = floor(((2N-1) - sqrt((2N-1)^2 - 8p)) / 2)
    const double twoNm1 = 2.0 * N_PART - 1.0;
    double disc = twoNm1 * twoNm1 - 8.0 * (double)p;
    int i = (int)((twoNm1 - sqrt(disc)) * 0.5);
    if (i > N_PART - 2) i = N_PART - 2;
    if (i < 0) i = 0;
    // one-ulp safety correction (0-1 iterations in practice; provably bounded)
    while (i < N_PART - 2 && row_off(i + 1) <= p) ++i;
    while (i > 0 && row_off(i) > p) --i;
    int j = i + 1 + (int)(p - row_off(i));

    // ---- displacement (positions tiny: fully L1/L2 resident; pos[i] warp-uniform) ----
    float xi = __ldg(&pos[3 * i + 0]);
    float yi = __ldg(&pos[3 * i + 1]);
    float zi = __ldg(&pos[3 * i + 2]);
    float xj = __ldg(&pos[3 * j + 0]);
    float yj = __ldg(&pos[3 * j + 1]);
    float zj = __ldg(&pos[3 * j + 2]);

    float rx = __fadd_rn(xi, -xj);
    float ry = __fadd_rn(yi, -yj);
    float rz = __fadd_rn(zi, -zj);

    if (__ldg(is_periodic)) {
        float Lx = __ldg(&box[0]);
        float Ly = __ldg(&box[4]);
        float Lz = __ldg(&box[8]);
        rx = floormod_wrap(rx, Lx, __fmul_rn(Lx, 0.5f));
        ry = floormod_wrap(ry, Ly, __fmul_rn(Ly, 0.5f));
        rz = floormod_wrap(rz, Lz, __fmul_rn(Lz, 0.5f));
    }

    // XLA order: rounded squares, then ((x2 + y2) + z2). No FMA contraction.
    float x2 = __fmul_rn(rx, rx);
    float y2 = __fmul_rn(ry, ry);
    float z2 = __fmul_rn(rz, rz);
    float d2 = __fadd_rn(__fadd_rn(x2, y2), z2);
    float d  = __fsqrt_rn(d2);
    bool in_cut = (d <= CUTOFF_F);

    float* __restrict__ oi  = out;                 // i indices
    float* __restrict__ oj  = out + P_TOTAL;       // j indices
    float* __restrict__ od  = out + 2 * P_TOTAL;   // distances
    float* __restrict__ orr = out + 3 * P_TOTAL;   // displacements [P,3]

    if (in_cut) {
        oi[p] = (float)i;
        oj[p] = (float)j;
        od[p] = d;
        orr[3 * p + 0] = rx;
        orr[3 * p + 1] = ry;
        orr[3 * p + 2] = rz;
    } else {
        oi[p] = -1.0f;
        oj[p] = -1.0f;
        od[p] = 0.0f;
        orr[3 * p + 0] = 0.0f;
        orr[3 * p + 1] = 0.0f;
        orr[3 * p + 2] = 0.0f;
    }
}

extern "C" void kernel_launch(void* const* d_in, const int* in_sizes, int n_in,
                              void* d_out, int out_size)
{
    const float* pos = (const float*)d_in[0];       // [6000, 3] float32
    const float* box = (const float*)d_in[1];       // [3, 3] float32
    const int*   per = (const int*)d_in[2];         // scalar int32

    float* out = (float*)d_out;

    const int threads = 256;
    const long long blocks = (P_TOTAL + threads - 1) / threads;   // 70,301
    neighborlist_kernel<<<(unsigned int)blocks, threads>>>(pos, box, per, out);
}

// round 7
// speedup vs baseline: 5.3481x; 5.3481x over previous
#include <cuda_runtime.h>
#include <cstdint>

// Neighborlist brute N^2, upper-triangular pairs, PBC minimum image.
// N=6000 -> P = 17,997,000 pairs (divisible by 4).
// Output buffer: float32, concatenation of the reference tuple:
//   [0,    P)   : masked i indices (-1 if out of cutoff)
//   [P,   2P)   : masked j indices
//   [2P,  3P)   : d_ij (0 if out of cutoff)
//   [3P,  6P)   : r_ij row-major [P,3] (0 if out of cutoff)
//
// Each thread processes 4 consecutive pairs: one index inversion per thread,
// all 24 output floats written as 6 STG.128.

#define N_PART   6000
#define P_TOTAL  17997000LL   // N*(N-1)/2
#define CUTOFF_F 0.5f
#define PAIRS_PER_THREAD 4LL
#define N_THREADS_TOTAL  (P_TOTAL / PAIRS_PER_THREAD)   // 4,499,250

__device__ __forceinline__ long long row_off(int i) {
    // offset of first pair of row i in triu(k=1) ordering
    return (long long)i * (2 * N_PART - i - 1) / 2;
}

// Bitwise-identical to: m = fmodf(r + halfL, L); if (m != 0 && m < 0) m += L;
// return m - halfL;   -- valid for t = r + halfL in (-L, 2L), which holds since
// positions are in [0, L)  =>  r in (-L, L), t in (-L/2, 3L/2).
//   t >= L : fmod = t - L   (Sterbenz: t in [L, 2L) => t-L exact = true remainder)
//   0<=t<L : fmod = t
//   t <  0 : fmod = t (exact, |t| < L), correction adds L with rn rounding
__device__ __forceinline__ float floormod_wrap(float r, float L, float halfL) {
    float t = __fadd_rn(r, halfL);
    float m = t;
    m = (t >= L)   ? __fadd_rn(t, -L) : m;
    m = (t < 0.0f) ? __fadd_rn(t,  L) : m;
    return __fadd_rn(m, -halfL);
}

__global__ __launch_bounds__(256)
void neighborlist_kernel(const float* __restrict__ pos,
                         const float* __restrict__ box,
                         const int* __restrict__ is_periodic,
                         float* __restrict__ out)
{
    long long t = (long long)blockIdx.x * blockDim.x + threadIdx.x;
    if (t >= N_THREADS_TOTAL) return;
    long long p0 = t * PAIRS_PER_THREAD;

    // ---- invert p0 -> (i, j), once per thread, all-f32 + int64 fixup ----
    // off(i) = i*(2N-1-i)/2 <= p  =>  i ~ ((2N-1) - sqrt((2N-1)^2 - 8p)) / 2
    const double twoNm1 = 2.0 * N_PART - 1.0;
    double disc_d = twoNm1 * twoNm1 - 8.0 * (double)p0;   // exact in double
    float  s = __fsqrt_rn((float)disc_d);
    int i = (int)(((float)twoNm1 - s) * 0.5f);
    if (i > N_PART - 2) i = N_PART - 2;
    if (i < 0) i = 0;
    while (i < N_PART - 2 && row_off(i + 1) <= p0) ++i;   // bounded fixup (<=2 iters)
    while (i > 0 && row_off(i) > p0) --i;
    int j = i + 1 + (int)(p0 - row_off(i));

    const int periodic = __ldg(is_periodic);
    const float Lx = __ldg(&box[0]);
    const float Ly = __ldg(&box[4]);
    const float Lz = __ldg(&box[8]);
    const float hx = __fmul_rn(Lx, 0.5f);
    const float hy = __fmul_rn(Ly, 0.5f);
    const float hz = __fmul_rn(Lz, 0.5f);

    float fi[4], fj[4], fd[4], fr[12];

    #pragma unroll
    for (int k = 0; k < 4; ++k) {
        float xi = __ldg(&pos[3 * i + 0]);
        float yi = __ldg(&pos[3 * i + 1]);
        float zi = __ldg(&pos[3 * i + 2]);
        float xj = __ldg(&pos[3 * j + 0]);
        float yj = __ldg(&pos[3 * j + 1]);
        float zj = __ldg(&pos[3 * j + 2]);

        float rx = __fadd_rn(xi, -xj);
        float ry = __fadd_rn(yi, -yj);
        float rz = __fadd_rn(zi, -zj);

        if (periodic) {
            rx = floormod_wrap(rx, Lx, hx);
            ry = floormod_wrap(ry, Ly, hy);
            rz = floormod_wrap(rz, Lz, hz);
        }

        // XLA order: rounded squares, then ((x2 + y2) + z2). No FMA contraction.
        float x2 = __fmul_rn(rx, rx);
        float y2 = __fmul_rn(ry, ry);
        float z2 = __fmul_rn(rz, rz);
        float d2 = __fadd_rn(__fadd_rn(x2, y2), z2);
        float d  = __fsqrt_rn(d2);
        bool in_cut = (d <= CUTOFF_F);

        fi[k] = in_cut ? (float)i : -1.0f;
        fj[k] = in_cut ? (float)j : -1.0f;
        fd[k] = in_cut ? d : 0.0f;
        fr[3 * k + 0] = in_cut ? rx : 0.0f;
        fr[3 * k + 1] = in_cut ? ry : 0.0f;
        fr[3 * k + 2] = in_cut ? rz : 0.0f;

        // advance (i, j): after (i, N-1) comes (i+1, i+2)
        ++j;
        if (j >= N_PART) { ++i; j = i + 1; }
    }

    // ---- vectorized stores: p0 % 4 == 0 and all region bases % 4 == 0 ----
    float4* oi  = (float4*)(out + p0);
    float4* oj  = (float4*)(out + P_TOTAL + p0);
    float4* od  = (float4*)(out + 2 * P_TOTAL + p0);
    float4* orr = (float4*)(out + 3 * P_TOTAL + 3 * p0);

    *oi = make_float4(fi[0], fi[1], fi[2], fi[3]);
    *oj = make_float4(fj[0], fj[1], fj[2], fj[3]);
    *od = make_float4(fd[0], fd[1], fd[2], fd[3]);
    orr[0] = make_float4(fr[0], fr[1], fr[2],  fr[3]);
    orr[1] = make_float4(fr[4], fr[5], fr[6],  fr[7]);
    orr[2] = make_float4(fr[8], fr[9], fr[10], fr[11]);
}

extern "C" void kernel_launch(void* const* d_in, const int* in_sizes, int n_in,
                              void* d_out, int out_size)
{
    const float* pos = (const float*)d_in[0];       // [6000, 3] float32
    const float* box = (const float*)d_in[1];       // [3, 3] float32
    const int*   per = (const int*)d_in[2];         // scalar int32

    float* out = (float*)d_out;

    const int threads = 256;
    const long long blocks = (N_THREADS_TOTAL + threads - 1) / threads;  // 17,576
    neighborlist_kernel<<<(unsigned int)blocks, threads>>>(pos, box, per, out);
}